// round 2
// baseline (speedup 1.0000x reference)
#include <cuda_runtime.h>
#include <cstdint>

#define D_DIM   512
#define K_DIM   112
#define SD      516              // padded SMEM row stride in floats (16B-aligned, banks spread)
#define NTHREADS 448
#define KPP     28               // k per pass
#define NPASS   4                // KPP*NPASS == K_DIM
#define LAMBDA_ 5.0f
#define SMEM_BYTES (SD * K_DIM * 4)

__device__ __forceinline__ unsigned long long fma2(unsigned long long a,
                                                   unsigned long long b,
                                                   unsigned long long c) {
    unsigned long long d;
    asm("fma.rn.f32x2 %0, %1, %2, %3;" : "=l"(d) : "l"(a), "l"(b), "l"(c));
    return d;
}

__global__ __launch_bounds__(NTHREADS, 1)
void tse_kernel(const float* __restrict__ x,
                const float* __restrict__ cc,
                float* __restrict__ out, int B)
{
    extern __shared__ float Csh[];
    const int tid = threadIdx.x;

    // Cooperative load of cluster centers into padded SMEM (112 x 512, stride 516).
    #pragma unroll
    for (int i = 0; i < (K_DIM * D_DIM / 4) / NTHREADS; i++) {
        int idx = i * NTHREADS + tid;          // 0 .. 14335
        int kr  = idx >> 7;                    // / (512/4)
        int c4  = idx & 127;
        float4 v = reinterpret_cast<const float4*>(cc)[idx];
        *reinterpret_cast<float4*>(&Csh[kr * SD + (c4 << 2)]) = v;
    }
    __syncthreads();

    const int row = blockIdx.x * NTHREADS + tid;
    if (row >= B) return;

    const ulonglong2* __restrict__ xr =
        reinterpret_cast<const ulonglong2*>(x + (size_t)row * D_DIM);

    // top-5 (value, index), v0 >= v1 >= ... >= v4
    float v0 = -1e30f, v1 = -1e30f, v2 = -1e30f, v3 = -1e30f, v4 = -1e30f;
    int   i0 = 0, i1 = 0, i2 = 0, i3 = 0, i4 = 0;

    #pragma unroll
    for (int p = 0; p < NPASS; p++) {
        unsigned long long acc[KPP];
        #pragma unroll
        for (int k = 0; k < KPP; k++) acc[k] = 0ull;   // packed (0.f, 0.f)

        const float* cb = &Csh[(p * KPP) * SD];

        for (int db = 0; db < D_DIM / 4; db++) {
            ulonglong2 xv = xr[db];                    // (x[d],x[d+1]) , (x[d+2],x[d+3])
            #pragma unroll
            for (int k = 0; k < KPP; k++) {
                // broadcast LDS.128: all lanes read the same address
                ulonglong2 cv = *reinterpret_cast<const ulonglong2*>(cb + k * SD + db * 4);
                acc[k] = fma2(xv.x, cv.x, acc[k]);
                acc[k] = fma2(xv.y, cv.y, acc[k]);
            }
        }

        #pragma unroll
        for (int k = 0; k < KPP; k++) {
            float lo = __uint_as_float((unsigned)(acc[k] & 0xffffffffull));
            float hi = __uint_as_float((unsigned)(acc[k] >> 32));
            float s  = lo + hi;
            int  kk  = p * KPP + k;
            if (s > v4) {   // strict > : earlier index wins ties (matches jax top_k)
                v4 = s; i4 = kk;
                if (v4 > v3) { float t=v3; v3=v4; v4=t; int ti=i3; i3=i4; i4=ti; }
                if (v3 > v2) { float t=v2; v2=v3; v3=t; int ti=i2; i2=i3; i3=ti; }
                if (v2 > v1) { float t=v1; v1=v2; v2=t; int ti=i1; i1=i2; i2=ti; }
                if (v1 > v0) { float t=v0; v0=v1; v1=t; int ti=i0; i0=i1; i1=ti; }
            }
        }
    }

    // softmax over the 5 selected sims (re-score einsum == sims), fold lambda in
    float e0 = 1.0f;
    float e1 = __expf(v1 - v0);
    float e2 = __expf(v2 - v0);
    float e3 = __expf(v3 - v0);
    float e4 = __expf(v4 - v0);
    float inv = LAMBDA_ / (e0 + e1 + e2 + e3 + e4);
    float w0 = e0 * inv, w1 = e1 * inv, w2 = e2 * inv, w3 = e3 * inv, w4 = e4 * inv;

    const float* c0 = &Csh[i0 * SD];
    const float* c1 = &Csh[i1 * SD];
    const float* c2 = &Csh[i2 * SD];
    const float* c3 = &Csh[i3 * SD];
    const float* c4 = &Csh[i4 * SD];

    const float4* __restrict__ x4 = reinterpret_cast<const float4*>(x + (size_t)row * D_DIM);
    float4* __restrict__ o4 = reinterpret_cast<float4*>(out + (size_t)row * D_DIM);

    for (int db = 0; db < D_DIM / 4; db++) {
        float4 xv = x4[db];
        float4 a0 = *reinterpret_cast<const float4*>(c0 + db * 4);
        float4 a1 = *reinterpret_cast<const float4*>(c1 + db * 4);
        float4 a2 = *reinterpret_cast<const float4*>(c2 + db * 4);
        float4 a3 = *reinterpret_cast<const float4*>(c3 + db * 4);
        float4 a4 = *reinterpret_cast<const float4*>(c4 + db * 4);
        float4 o;
        o.x = xv.x + w0*a0.x + w1*a1.x + w2*a2.x + w3*a3.x + w4*a4.x;
        o.y = xv.y + w0*a0.y + w1*a1.y + w2*a2.y + w3*a3.y + w4*a4.y;
        o.z = xv.z + w0*a0.z + w1*a1.z + w2*a2.z + w3*a3.z + w4*a4.z;
        o.w = xv.w + w0*a0.w + w1*a1.w + w2*a2.w + w3*a3.w + w4*a4.w;
        o4[db] = o;
    }
}

extern "C" void kernel_launch(void* const* d_in, const int* in_sizes, int n_in,
                              void* d_out, int out_size)
{
    const float* x  = (const float*)d_in[0];
    const float* cc = (const float*)d_in[1];
    int B = in_sizes[0] / D_DIM;

    cudaFuncSetAttribute(tse_kernel, cudaFuncAttributeMaxDynamicSharedMemorySize, SMEM_BYTES);

    int grid = (B + NTHREADS - 1) / NTHREADS;   // 293 for B=131072
    tse_kernel<<<grid, NTHREADS, SMEM_BYTES>>>(x, cc, (float*)d_out, B);
}

// round 3
// speedup vs baseline: 1.1838x; 1.1838x over previous
#include <cuda_runtime.h>
#include <cstdint>

#define D_DIM   512
#define K_DIM   112
#define BM      128
#define BK      16
#define NTHR    256
#define XS_STRIDE   132              // padded, 16B-aligned rows
#define CS_STRIDE   116
#define SIMS_STRIDE 113              // odd -> conflict-free column scans
#define LAMBDA_ 5.0f

#define XS_FLOATS     (BK * XS_STRIDE)                 // 2112
#define SIMS_FLOATS   (BM * SIMS_STRIDE)               // 14464
#define W5_OFF        SIMS_FLOATS
#define I5_OFF        (SIMS_FLOATS + BM * 5)
#define SMEM_FLOATS   (SIMS_FLOATS + BM * 5 * 2)       // 15744 floats
#define SMEM_BYTES    (SMEM_FLOATS * 4)                // 62976 B

__device__ __forceinline__ unsigned long long fma2(unsigned long long a,
                                                   unsigned long long b,
                                                   unsigned long long c) {
    unsigned long long d;
    asm("fma.rn.f32x2 %0, %1, %2, %3;" : "=l"(d) : "l"(a), "l"(b), "l"(c));
    return d;
}

__device__ __forceinline__ unsigned long long dup2(float a) {
    unsigned long long r;
    asm("mov.b64 %0, {%1, %1};" : "=l"(r) : "f"(a));
    return r;
}

__global__ __launch_bounds__(NTHR, 2)
void tse_gemm_kernel(const float* __restrict__ x,
                     const float* __restrict__ cc,
                     float* __restrict__ out)
{
    extern __shared__ float sm[];
    float* xs = sm;                    // [BK][XS_STRIDE]  x tile (depth-major)
    float* cs = sm + XS_FLOATS;        // [BK][CS_STRIDE]  C tile (depth-major)

    const int tid  = threadIdx.x;
    const int tcol = tid & 7;          // 8 col-groups * 14 cols  = 112
    const int trow = tid >> 3;         // 32 row-groups * 4 rows  = 128
    const int row0 = blockIdx.x * BM;

    unsigned long long acc[4][7];
    #pragma unroll
    for (int i = 0; i < 4; i++)
        #pragma unroll
        for (int j = 0; j < 7; j++) acc[i][j] = 0ull;

    // register prefetch buffers
    float4 px[2], pc[2];
    const int xgid0 = tid, xgid1 = NTHR + tid;              // 0..511 : 128 rows x 4 quads
    const int cgid0 = tid, cgid1 = NTHR + tid;              // 0..447 : 112 centers x 4 quads

    auto FETCH = [&](int kb) {
        px[0] = *(const float4*)&x[(size_t)(row0 + (xgid0 >> 2)) * D_DIM + kb * BK + (xgid0 & 3) * 4];
        px[1] = *(const float4*)&x[(size_t)(row0 + (xgid1 >> 2)) * D_DIM + kb * BK + (xgid1 & 3) * 4];
        pc[0] = *(const float4*)&cc[(size_t)(cgid0 >> 2) * D_DIM + kb * BK + (cgid0 & 3) * 4];
        if (cgid1 < K_DIM * 4)
            pc[1] = *(const float4*)&cc[(size_t)(cgid1 >> 2) * D_DIM + kb * BK + (cgid1 & 3) * 4];
    };

    auto STORE = [&]() {
        {
            int r = xgid0 >> 2, dq = (xgid0 & 3) * 4;
            xs[(dq + 0) * XS_STRIDE + r] = px[0].x;
            xs[(dq + 1) * XS_STRIDE + r] = px[0].y;
            xs[(dq + 2) * XS_STRIDE + r] = px[0].z;
            xs[(dq + 3) * XS_STRIDE + r] = px[0].w;
            r = xgid1 >> 2; dq = (xgid1 & 3) * 4;
            xs[(dq + 0) * XS_STRIDE + r] = px[1].x;
            xs[(dq + 1) * XS_STRIDE + r] = px[1].y;
            xs[(dq + 2) * XS_STRIDE + r] = px[1].z;
            xs[(dq + 3) * XS_STRIDE + r] = px[1].w;
        }
        {
            int c = cgid0 >> 2, dq = (cgid0 & 3) * 4;
            cs[(dq + 0) * CS_STRIDE + c] = pc[0].x;
            cs[(dq + 1) * CS_STRIDE + c] = pc[0].y;
            cs[(dq + 2) * CS_STRIDE + c] = pc[0].z;
            cs[(dq + 3) * CS_STRIDE + c] = pc[0].w;
            if (cgid1 < K_DIM * 4) {
                c = cgid1 >> 2; dq = (cgid1 & 3) * 4;
                cs[(dq + 0) * CS_STRIDE + c] = pc[1].x;
                cs[(dq + 1) * CS_STRIDE + c] = pc[1].y;
                cs[(dq + 2) * CS_STRIDE + c] = pc[1].z;
                cs[(dq + 3) * CS_STRIDE + c] = pc[1].w;
            }
        }
    };

    FETCH(0);
    for (int kb = 0; kb < D_DIM / BK; kb++) {
        __syncthreads();
        STORE();
        __syncthreads();
        if (kb + 1 < D_DIM / BK) FETCH(kb + 1);   // LDGs overlap compute below

        #pragma unroll
        for (int kk = 0; kk < BK; kk++) {
            float4 av = *(const float4*)&xs[kk * XS_STRIDE + trow * 4];
            unsigned long long a0 = dup2(av.x), a1 = dup2(av.y),
                               a2 = dup2(av.z), a3 = dup2(av.w);
            const unsigned long long* bp =
                (const unsigned long long*)&cs[kk * CS_STRIDE + tcol * 14];
            #pragma unroll
            for (int j = 0; j < 7; j++) {
                unsigned long long b = bp[j];
                acc[0][j] = fma2(a0, b, acc[0][j]);
                acc[1][j] = fma2(a1, b, acc[1][j]);
                acc[2][j] = fma2(a2, b, acc[2][j]);
                acc[3][j] = fma2(a3, b, acc[3][j]);
            }
        }
    }

    // ---- dump sims to SMEM (overlay tiles) ----
    __syncthreads();
    float* sims = sm;
    #pragma unroll
    for (int i = 0; i < 4; i++) {
        int r = trow * 4 + i;
        #pragma unroll
        for (int j = 0; j < 7; j++) {
            unsigned long long v = acc[i][j];
            sims[r * SIMS_STRIDE + tcol * 14 + 2 * j]     = __uint_as_float((unsigned)(v & 0xffffffffull));
            sims[r * SIMS_STRIDE + tcol * 14 + 2 * j + 1] = __uint_as_float((unsigned)(v >> 32));
        }
    }
    __syncthreads();

    // ---- per-row top-5 + softmax ----
    float* w5 = sm + W5_OFF;
    int*   i5 = (int*)(sm + I5_OFF);
    if (tid < BM) {
        const float* sr = &sims[tid * SIMS_STRIDE];
        float v0 = -1e30f, v1 = -1e30f, v2 = -1e30f, v3 = -1e30f, v4 = -1e30f;
        int   i0 = 0, i1 = 0, i2 = 0, i3 = 0, i4 = 0;
        for (int c = 0; c < K_DIM; c++) {
            float s = sr[c];
            if (s > v4) {                               // strict >: earliest index wins ties
                v4 = s; i4 = c;
                if (v4 > v3) { float t=v3; v3=v4; v4=t; int ti=i3; i3=i4; i4=ti; }
                if (v3 > v2) { float t=v2; v2=v3; v3=t; int ti=i2; i2=i3; i3=ti; }
                if (v2 > v1) { float t=v1; v1=v2; v2=t; int ti=i1; i1=i2; i2=ti; }
                if (v1 > v0) { float t=v0; v0=v1; v1=t; int ti=i0; i0=i1; i1=ti; }
            }
        }
        float e0 = 1.0f;
        float e1 = __expf(v1 - v0);
        float e2 = __expf(v2 - v0);
        float e3 = __expf(v3 - v0);
        float e4 = __expf(v4 - v0);
        float inv = LAMBDA_ / (e0 + e1 + e2 + e3 + e4);
        w5[tid * 5 + 0] = e0 * inv;  i5[tid * 5 + 0] = i0;
        w5[tid * 5 + 1] = e1 * inv;  i5[tid * 5 + 1] = i1;
        w5[tid * 5 + 2] = e2 * inv;  i5[tid * 5 + 2] = i2;
        w5[tid * 5 + 3] = e3 * inv;  i5[tid * 5 + 3] = i3;
        w5[tid * 5 + 4] = e4 * inv;  i5[tid * 5 + 4] = i4;
    }
    __syncthreads();

    // ---- epilogue: out = x + sum w_j * C[idx_j]   (2 threads per row) ----
    {
        int r = tid >> 1;
        int h = tid & 1;
        float w0 = w5[r*5+0], w1 = w5[r*5+1], w2 = w5[r*5+2], w3 = w5[r*5+3], w4 = w5[r*5+4];
        int   j0 = i5[r*5+0], j1 = i5[r*5+1], j2 = i5[r*5+2], j3 = i5[r*5+3], j4 = i5[r*5+4];

        size_t grow = (size_t)(row0 + r) * D_DIM + h * 256;
        const float4* xp = (const float4*)&x[grow];
        float4*       op = (float4*)&out[grow];
        const float4* c0 = (const float4*)&cc[(size_t)j0 * D_DIM + h * 256];
        const float4* c1 = (const float4*)&cc[(size_t)j1 * D_DIM + h * 256];
        const float4* c2 = (const float4*)&cc[(size_t)j2 * D_DIM + h * 256];
        const float4* c3 = (const float4*)&cc[(size_t)j3 * D_DIM + h * 256];
        const float4* c4 = (const float4*)&cc[(size_t)j4 * D_DIM + h * 256];

        #pragma unroll 4
        for (int q = 0; q < 64; q++) {
            float4 xv = xp[q];
            float4 a0 = c0[q], a1 = c1[q], a2 = c2[q], a3 = c3[q], a4 = c4[q];
            float4 o;
            o.x = xv.x + w0*a0.x + w1*a1.x + w2*a2.x + w3*a3.x + w4*a4.x;
            o.y = xv.y + w0*a0.y + w1*a1.y + w2*a2.y + w3*a3.y + w4*a4.y;
            o.z = xv.z + w0*a0.z + w1*a1.z + w2*a2.z + w3*a3.z + w4*a4.z;
            o.w = xv.w + w0*a0.w + w1*a1.w + w2*a2.w + w3*a3.w + w4*a4.w;
            op[q] = o;
        }
    }
}

extern "C" void kernel_launch(void* const* d_in, const int* in_sizes, int n_in,
                              void* d_out, int out_size)
{
    const float* x  = (const float*)d_in[0];
    const float* cc = (const float*)d_in[1];
    int B = in_sizes[0] / D_DIM;

    cudaFuncSetAttribute(tse_gemm_kernel, cudaFuncAttributeMaxDynamicSharedMemorySize, SMEM_BYTES);

    int grid = B / BM;                 // 1024 for B=131072
    tse_gemm_kernel<<<grid, NTHR, SMEM_BYTES>>>(x, cc, (float*)d_out);
}